// round 8
// baseline (speedup 1.0000x reference)
#include <cuda_runtime.h>
#include <cuda_bf16.h>
#include <cstdint>

// ---------------------------------------------------------------------------
// Problem constants
// ---------------------------------------------------------------------------
#define D_IN   992
#define HID    32
#define NKS    62            // 992 / 16 k-steps
#define KSPLIT 31            // k-steps per warp (2-way split)
#define TMROWS 128           // rows per CTA

// W in mma B-fragment layout (k-permuted), bf16 hi/lo packed per lane:
// [ks 62][nt 4][lane 32] -> uint4 (bh0, bh1, bl0, bl1)
__device__ uint4 g_Wf[NKS * 4 * 32];

// ---------------------------------------------------------------------------
// helpers
// ---------------------------------------------------------------------------
__device__ __forceinline__ uint32_t packbf(float e0, float e1) {
    uint32_t r;
    asm("cvt.rn.bf16x2.f32 %0, %1, %2;" : "=r"(r) : "f"(e1), "f"(e0));
    return r;
}
__device__ __forceinline__ void unpackbf(uint32_t p, float& e0, float& e1) {
    e0 = __uint_as_float(p << 16);
    e1 = __uint_as_float(p & 0xFFFF0000u);
}
__device__ __forceinline__ void mma_bf16(float d[4], uint32_t a0, uint32_t a1,
                                         uint32_t a2, uint32_t a3,
                                         uint32_t b0, uint32_t b1) {
    asm volatile(
        "mma.sync.aligned.m16n8k16.row.col.f32.bf16.bf16.f32 "
        "{%0,%1,%2,%3}, {%4,%5,%6,%7}, {%8,%9}, {%0,%1,%2,%3};"
        : "+f"(d[0]), "+f"(d[1]), "+f"(d[2]), "+f"(d[3])
        : "r"(a0), "r"(a1), "r"(a2), "r"(a3), "r"(b0), "r"(b1));
}

// f32x2 packed helpers (KAN phase)
__device__ __forceinline__ uint64_t f2dup(float x) {
    uint64_t r; asm("mov.b64 %0, {%1, %1};" : "=l"(r) : "f"(x)); return r;
}
__device__ __forceinline__ void f2unpack(uint64_t v, float& x, float& y) {
    asm("mov.b64 {%0, %1}, %2;" : "=f"(x), "=f"(y) : "l"(v));
}
__device__ __forceinline__ void ffma2(uint64_t& d, uint64_t a, uint64_t b) {
    asm("fma.rn.f32x2 %0, %1, %2, %0;" : "+l"(d) : "l"(a), "l"(b));
}

// degree-4 uniform B-spline basis (5 nonzero values), matches reference
__device__ __forceinline__ void bspline4(float u, float bw[5]) {
    const float um = 1.f - u;
    float c0 = um, c1 = u;
    float d0 = 0.5f * (um * c0);
    float d1 = 0.5f * ((u + 1.f) * c0 + (2.f - u) * c1);
    float d2 = 0.5f * (u * c1);
    const float i3 = 1.f / 3.f;
    float e0 = i3 * (um * d0);
    float e1 = i3 * ((u + 2.f) * d0 + (2.f - u) * d1);
    float e2 = i3 * ((u + 1.f) * d1 + (3.f - u) * d2);
    float e3 = i3 * (u * d2);
    bw[0] = 0.25f * (um * e0);
    bw[1] = 0.25f * ((u + 3.f) * e0 + (2.f - u) * e1);
    bw[2] = 0.25f * ((u + 2.f) * e1 + (3.f - u) * e2);
    bw[3] = 0.25f * ((u + 1.f) * e2 + (4.f - u) * e3);
    bw[4] = 0.25f * (u * e3);
}
__device__ __forceinline__ float silu_f(float x) { return x / (1.f + __expf(-x)); }

// ---------------------------------------------------------------------------
// W pre-conversion with k-permutation:
// lane (g,t4), nt: b0 = {W[ks16+4t4][n], W[ks16+4t4+1][n]},
//                  b1 = {W[ks16+4t4+2][n], W[ks16+4t4+3][n]}, n = nt*8+g
// ---------------------------------------------------------------------------
__global__ void wfrag_kernel(const float* __restrict__ W) {
    int idx = blockIdx.x * 256 + threadIdx.x;     // 62*4*32 = 7936
    if (idx >= NKS * 4 * 32) return;
    int lane = idx & 31;
    int nt   = (idx >> 5) & 3;
    int ks   = idx >> 7;
    int g = lane >> 2, t4 = lane & 3;
    int n  = nt * 8 + g;
    int ka = ks * 16 + t4 * 4;

    float x0 = W[(ka + 0) * HID + n];
    float x1 = W[(ka + 1) * HID + n];
    float y0 = W[(ka + 2) * HID + n];
    float y1 = W[(ka + 3) * HID + n];

    uint32_t h0 = packbf(x0, x1), h1 = packbf(y0, y1);
    float e0, e1;
    unpackbf(h0, e0, e1);
    uint32_t l0 = packbf(x0 - e0, x1 - e1);
    unpackbf(h1, e0, e1);
    uint32_t l1 = packbf(y0 - e0, y1 - e1);

    g_Wf[idx] = make_uint4(h0, h1, l0, l1);
}

// ---------------------------------------------------------------------------
// Fused kernel (R6 backbone + depth-2 A register prefetch, W loaded in-step):
//   warp w (w<4)  : m-tiles 2w, 2w+1 (rows w*32..w*32+31), k-steps 0..30
//   warp w+4      : same m-tiles,                          k-steps 31..61
// One W fragment load feeds 2 m-tiles; each warp walks only half the k-range.
// ---------------------------------------------------------------------------
__global__ void __launch_bounds__(256, 2)
fused_kernel(const float* __restrict__ A, const float* __restrict__ bias,
             const float* __restrict__ coef0, const float* __restrict__ wb0,
             const float* __restrict__ ws0,   const float* __restrict__ b0,
             const float* __restrict__ coef1, const float* __restrict__ wb1,
             const float* __restrict__ ws1,   const float* __restrict__ b1,
             float* __restrict__ out, int N)
{
    __shared__ __align__(16) float hs[TMROWS * 33];      // hidden, stride 33
    __shared__ __align__(16) float pp[TMROWS * 33];      // partials / KAN ps
    __shared__ __align__(16) float cw0s[32 * 12 * 6];    // coef0*ws0 [i][j][o6]
    __shared__ __align__(16) float wb0s[32 * 6];
    __shared__ __align__(16) float cw1s[6 * 12];
    __shared__ float wb1s[6], b0s[6], b1s[1];

    const int tid  = threadIdx.x;
    const int warp = tid >> 5;
    const int lane = tid & 31;
    const int g    = lane >> 2;
    const int t4   = lane & 3;
    const int wp   = warp & 3;        // m-pair id (rows wp*32..wp*32+31)
    const int kh   = warp >> 2;       // k-half (0: steps 0..30, 1: 31..61)
    const int off  = kh * KSPLIT;
    const int row0 = blockIdx.x * TMROWS;

    // ---- stage KAN tables ----
    for (int idx = tid; idx < 32 * 12 * 6; idx += 256) {
        int i = idx / 72, rem = idx % 72, j = rem / 6, o = rem % 6;
        cw0s[idx] = coef0[(i * 6 + o) * 12 + j] * ws0[i * 6 + o];
    }
    if (tid < 32 * 6) wb0s[tid] = wb0[tid];
    if (tid < 72) cw1s[tid] = coef1[tid] * ws1[tid / 12];
    if (tid < 6)  { wb1s[tid] = wb1[tid]; b0s[tid] = b0[tid]; }
    if (tid == 0) b1s[0] = b1[0];

    // ---- A row pointers for the 2 m-tiles ----
    const float* pA[2][2];
    #pragma unroll
    for (int mt = 0; mt < 2; mt++) {
        int r0 = row0 + (wp * 2 + mt) * 16 + g;
        int r1 = r0 + 8;
        if (r0 > N - 1) r0 = N - 1;
        if (r1 > N - 1) r1 = N - 1;
        pA[mt][0] = A + (size_t)r0 * D_IN + t4 * 4;
        pA[mt][1] = A + (size_t)r1 * D_IN + t4 * 4;
    }

    // ---- depth-2 A prefetch: av[buf][mt][half] ----
    float4 av[2][2][2];
    #pragma unroll
    for (int b = 0; b < 2; b++)
        #pragma unroll
        for (int mt = 0; mt < 2; mt++) {
            av[b][mt][0] = __ldcs((const float4*)(pA[mt][0] + (off + b) * 16));
            av[b][mt][1] = __ldcs((const float4*)(pA[mt][1] + (off + b) * 16));
        }

    float acc[2][4][4];
    #pragma unroll
    for (int mt = 0; mt < 2; mt++)
        #pragma unroll
        for (int nt = 0; nt < 4; nt++)
            #pragma unroll
            for (int r = 0; r < 4; r++) acc[mt][nt][r] = 0.f;

    // ---- mainloop: 31 k-steps, barrier-free ----
    for (int s = 0; s < KSPLIT; s++) {
        const int cur = s & 1;

        // pull current step to temps, freeing the buffer
        float4 a0[2], a1[2];
        #pragma unroll
        for (int mt = 0; mt < 2; mt++) {
            a0[mt] = av[cur][mt][0];
            a1[mt] = av[cur][mt][1];
        }

        // refill buffer with step s+2 (issue DRAM fetch as early as possible)
        if (s + 2 < KSPLIT) {
            const int kn = off + s + 2;
            #pragma unroll
            for (int mt = 0; mt < 2; mt++) {
                av[cur][mt][0] = __ldcs((const float4*)(pA[mt][0] + kn * 16));
                av[cur][mt][1] = __ldcs((const float4*)(pA[mt][1] + kn * 16));
            }
        }

        // W fragments for this step (L1-resident, short latency)
        uint4 w[4];
        {
            const uint4* wq = &g_Wf[(size_t)((off + s) * 4) * 32 + lane];
            #pragma unroll
            for (int nt = 0; nt < 4; nt++) w[nt] = wq[nt * 32];
        }

        #pragma unroll
        for (int mt = 0; mt < 2; mt++) {
            uint32_t ah0 = packbf(a0[mt].x, a0[mt].y);
            uint32_t ah1 = packbf(a1[mt].x, a1[mt].y);
            uint32_t ah2 = packbf(a0[mt].z, a0[mt].w);
            uint32_t ah3 = packbf(a1[mt].z, a1[mt].w);

            float e0, e1;
            uint32_t al0, al1, al2, al3;
            unpackbf(ah0, e0, e1); al0 = packbf(a0[mt].x - e0, a0[mt].y - e1);
            unpackbf(ah1, e0, e1); al1 = packbf(a1[mt].x - e0, a1[mt].y - e1);
            unpackbf(ah2, e0, e1); al2 = packbf(a0[mt].z - e0, a0[mt].w - e1);
            unpackbf(ah3, e0, e1); al3 = packbf(a1[mt].z - e0, a1[mt].w - e1);

            #pragma unroll
            for (int nt = 0; nt < 4; nt++) {
                mma_bf16(acc[mt][nt], ah0, ah1, ah2, ah3, w[nt].x, w[nt].y);
                mma_bf16(acc[mt][nt], ah0, ah1, ah2, ah3, w[nt].z, w[nt].w);
                mma_bf16(acc[mt][nt], al0, al1, al2, al3, w[nt].x, w[nt].y);
            }
        }
    }

    // ---- combine halves: upper dumps partials, lower adds + bias + transpose
    if (kh == 1) {
        #pragma unroll
        for (int nt = 0; nt < 4; nt++)
            #pragma unroll
            for (int mt = 0; mt < 2; mt++) {
                int rl = (wp * 2 + mt) * 16 + g;
                int c0 = nt * 8 + t4 * 2;
                pp[rl * 33 + c0]           = acc[mt][nt][0];
                pp[rl * 33 + c0 + 1]       = acc[mt][nt][1];
                pp[(rl + 8) * 33 + c0]     = acc[mt][nt][2];
                pp[(rl + 8) * 33 + c0 + 1] = acc[mt][nt][3];
            }
    }
    __syncthreads();
    if (kh == 0) {
        #pragma unroll
        for (int nt = 0; nt < 4; nt++) {
            float2 bv = *(const float2*)&bias[nt * 8 + t4 * 2];
            #pragma unroll
            for (int mt = 0; mt < 2; mt++) {
                int rl = (wp * 2 + mt) * 16 + g;
                int c0 = nt * 8 + t4 * 2;
                hs[rl * 33 + c0]           = acc[mt][nt][0] + pp[rl * 33 + c0]           + bv.x;
                hs[rl * 33 + c0 + 1]       = acc[mt][nt][1] + pp[rl * 33 + c0 + 1]       + bv.y;
                hs[(rl + 8) * 33 + c0]     = acc[mt][nt][2] + pp[(rl + 8) * 33 + c0]     + bv.x;
                hs[(rl + 8) * 33 + c0 + 1] = acc[mt][nt][3] + pp[(rl + 8) * 33 + c0 + 1] + bv.y;
            }
        }
    }
    __syncthreads();

    // ---- KAN layer 0: 2 threads per row, each handles 16 of 32 inputs ----
    const int r = tid & 127;          // row within CTA
    const int h = tid >> 7;           // half (0: i 0..15, 1: i 16..31)

    uint64_t kacc[3];
    kacc[0] = kacc[1] = kacc[2] = 0ull;

    #pragma unroll
    for (int i2 = 0; i2 < 16; i2++) {
        const int i = h * 16 + i2;
        float x  = hs[r * 33 + i];
        float sg = silu_f(x);
        uint64_t sgd = f2dup(sg);
        const uint64_t* wbp = (const uint64_t*)&wb0s[i * 6];
        ffma2(kacc[0], sgd, wbp[0]);
        ffma2(kacc[1], sgd, wbp[1]);
        ffma2(kacc[2], sgd, wbp[2]);

        float t = (x + 2.f) * 4.f;
        if (t >= 0.f && t < 16.f) {
            float cf = floorf(t);
            int   c  = (int)cf;
            float u  = t - cf;
            float bw[5];
            bspline4(u, bw);
            #pragma unroll
            for (int k = 0; k < 5; k++) {
                int j = c - 4 + k;
                if (j >= 0 && j < 12) {
                    uint64_t bd = f2dup(bw[k]);
                    const uint64_t* cp = (const uint64_t*)&cw0s[i * 72 + j * 6];
                    ffma2(kacc[0], bd, cp[0]);
                    ffma2(kacc[1], bd, cp[1]);
                    ffma2(kacc[2], bd, cp[2]);
                }
            }
        }
    }
    __syncthreads();                     // pp free for reuse as partial buffer
    {
        float p0, p1, p2, p3, p4, p5;
        f2unpack(kacc[0], p0, p1);
        f2unpack(kacc[1], p2, p3);
        f2unpack(kacc[2], p4, p5);
        float* q = &pp[r * 12 + h * 6];
        q[0] = p0; q[1] = p1; q[2] = p2;
        q[3] = p3; q[4] = p4; q[5] = p5;
    }
    __syncthreads();

    // ---- KAN layer 1 (half 0 threads only) ----
    if (h == 0) {
        const int row = row0 + r;
        if (row < N) {
            float res = b1s[0];
            #pragma unroll
            for (int i = 0; i < 6; i++) {
                float x = pp[r * 12 + i] + pp[r * 12 + 6 + i] + b0s[i];
                res += silu_f(x) * wb1s[i];
                float t = (x + 2.f) * 4.f;
                if (t >= 0.f && t < 16.f) {
                    float cf = floorf(t);
                    int   c  = (int)cf;
                    float u  = t - cf;
                    float bw[5];
                    bspline4(u, bw);
                    #pragma unroll
                    for (int k = 0; k < 5; k++) {
                        int j = c - 4 + k;
                        if (j >= 0 && j < 12) res += bw[k] * cw1s[i * 12 + j];
                    }
                }
            }
            out[row] = res;
        }
    }
}

// ---------------------------------------------------------------------------
// Launch
// ---------------------------------------------------------------------------
extern "C" void kernel_launch(void* const* d_in, const int* in_sizes, int n_in,
                              void* d_out, int out_size)
{
    const float* node_rep = (const float*)d_in[0];
    const float* mlp_w    = (const float*)d_in[1];
    const float* mlp_b    = (const float*)d_in[2];
    const float* coef0    = (const float*)d_in[3];
    const float* wb0      = (const float*)d_in[4];
    const float* ws0      = (const float*)d_in[5];
    const float* b0       = (const float*)d_in[6];
    const float* coef1    = (const float*)d_in[7];
    const float* wb1      = (const float*)d_in[8];
    const float* ws1      = (const float*)d_in[9];
    const float* b1       = (const float*)d_in[10];

    int N = in_sizes[0] / D_IN;

    wfrag_kernel<<<(NKS * 4 * 32 + 255) / 256, 256>>>(mlp_w);
    fused_kernel<<<(N + TMROWS - 1) / TMROWS, 256>>>(
        node_rep, mlp_b, coef0, wb0, ws0, b0, coef1, wb1, ws1, b1,
        (float*)d_out, N);
}

// round 9
// speedup vs baseline: 1.2894x; 1.2894x over previous
#include <cuda_runtime.h>
#include <cuda_bf16.h>
#include <cstdint>

// ---------------------------------------------------------------------------
// Problem constants
// ---------------------------------------------------------------------------
#define D_IN   992
#define HID    32
#define NKS    62            // 992 / 16 k-steps
#define KSPLIT 31            // k-steps per warp (2-way split)
#define TMROWS 128           // rows per CTA

// W in mma B-fragment layout (k-permuted), bf16 hi/lo packed per lane:
// [ks 62][nt 4][lane 32] -> uint4 (bh0, bh1, bl0, bl1)
__device__ uint4 g_Wf[NKS * 4 * 32];

// ---------------------------------------------------------------------------
// dynamic smem layout (floats)
// ---------------------------------------------------------------------------
#define SM_HS   0                          // 128*33 = 4224
#define SM_PP   4224                       // 128*33 = 4224
#define SM_CW0  8448                       // 32*20*6 = 3840 (j padded -4..15)
#define SM_WB0  12288                      // 32*6 = 192
#define SM_CW1  12480                      // 6*20 = 120 (j padded)
#define SM_WB1  12600                      // 6
#define SM_B0   12606                      // 6
#define SM_B1   12612                      // 1
#define SM_TOTF 12616
#define SM_BYTES (SM_TOTF * 4)             // 50464

// ---------------------------------------------------------------------------
// helpers
// ---------------------------------------------------------------------------
__device__ __forceinline__ uint32_t packbf(float e0, float e1) {
    uint32_t r;
    asm("cvt.rn.bf16x2.f32 %0, %1, %2;" : "=r"(r) : "f"(e1), "f"(e0));
    return r;
}
__device__ __forceinline__ void unpackbf(uint32_t p, float& e0, float& e1) {
    e0 = __uint_as_float(p << 16);
    e1 = __uint_as_float(p & 0xFFFF0000u);
}
__device__ __forceinline__ void mma_bf16(float d[4], uint32_t a0, uint32_t a1,
                                         uint32_t a2, uint32_t a3,
                                         uint32_t b0, uint32_t b1) {
    asm volatile(
        "mma.sync.aligned.m16n8k16.row.col.f32.bf16.bf16.f32 "
        "{%0,%1,%2,%3}, {%4,%5,%6,%7}, {%8,%9}, {%0,%1,%2,%3};"
        : "+f"(d[0]), "+f"(d[1]), "+f"(d[2]), "+f"(d[3])
        : "r"(a0), "r"(a1), "r"(a2), "r"(a3), "r"(b0), "r"(b1));
}

// f32x2 packed helpers (KAN phase)
__device__ __forceinline__ uint64_t f2dup(float x) {
    uint64_t r; asm("mov.b64 %0, {%1, %1};" : "=l"(r) : "f"(x)); return r;
}
__device__ __forceinline__ void f2unpack(uint64_t v, float& x, float& y) {
    asm("mov.b64 {%0, %1}, %2;" : "=f"(x), "=f"(y) : "l"(v));
}
__device__ __forceinline__ void ffma2(uint64_t& d, uint64_t a, uint64_t b) {
    asm("fma.rn.f32x2 %0, %1, %2, %0;" : "+l"(d) : "l"(a), "l"(b));
}

// degree-4 uniform B-spline basis (5 nonzero values), matches reference
__device__ __forceinline__ void bspline4(float u, float bw[5]) {
    const float um = 1.f - u;
    float c0 = um, c1 = u;
    float d0 = 0.5f * (um * c0);
    float d1 = 0.5f * ((u + 1.f) * c0 + (2.f - u) * c1);
    float d2 = 0.5f * (u * c1);
    const float i3 = 1.f / 3.f;
    float e0 = i3 * (um * d0);
    float e1 = i3 * ((u + 2.f) * d0 + (2.f - u) * d1);
    float e2 = i3 * ((u + 1.f) * d1 + (3.f - u) * d2);
    float e3 = i3 * (u * d2);
    bw[0] = 0.25f * (um * e0);
    bw[1] = 0.25f * ((u + 3.f) * e0 + (2.f - u) * e1);
    bw[2] = 0.25f * ((u + 2.f) * e1 + (3.f - u) * e2);
    bw[3] = 0.25f * ((u + 1.f) * e2 + (4.f - u) * e3);
    bw[4] = 0.25f * (u * e3);
}
__device__ __forceinline__ float silu_f(float x) { return x / (1.f + __expf(-x)); }

// ---------------------------------------------------------------------------
// W pre-conversion with k-permutation:
// lane (g,t4), nt: b0 = {W[ks16+4t4][n], W[ks16+4t4+1][n]},
//                  b1 = {W[ks16+4t4+2][n], W[ks16+4t4+3][n]}, n = nt*8+g
// ---------------------------------------------------------------------------
__global__ void wfrag_kernel(const float* __restrict__ W) {
    int idx = blockIdx.x * 256 + threadIdx.x;     // 62*4*32 = 7936
    if (idx >= NKS * 4 * 32) return;
    int lane = idx & 31;
    int nt   = (idx >> 5) & 3;
    int ks   = idx >> 7;
    int g = lane >> 2, t4 = lane & 3;
    int n  = nt * 8 + g;
    int ka = ks * 16 + t4 * 4;

    float x0 = W[(ka + 0) * HID + n];
    float x1 = W[(ka + 1) * HID + n];
    float y0 = W[(ka + 2) * HID + n];
    float y1 = W[(ka + 3) * HID + n];

    uint32_t h0 = packbf(x0, x1), h1 = packbf(y0, y1);
    float e0, e1;
    unpackbf(h0, e0, e1);
    uint32_t l0 = packbf(x0 - e0, x1 - e1);
    unpackbf(h1, e0, e1);
    uint32_t l1 = packbf(y0 - e0, y1 - e1);

    g_Wf[idx] = make_uint4(h0, h1, l0, l1);
}

// ---------------------------------------------------------------------------
// Fused kernel (R6 GEMM backbone, KAN with padded-j tables):
//   warp w (w<4)  : m-tiles 2w, 2w+1 (rows w*32..w*32+31), k-steps 0..30
//   warp w+4      : same m-tiles,                          k-steps 31..61
// ---------------------------------------------------------------------------
__global__ void __launch_bounds__(256, 2)
fused_kernel(const float* __restrict__ A, const float* __restrict__ bias,
             const float* __restrict__ coef0, const float* __restrict__ wb0,
             const float* __restrict__ ws0,   const float* __restrict__ b0,
             const float* __restrict__ coef1, const float* __restrict__ wb1,
             const float* __restrict__ ws1,   const float* __restrict__ b1,
             float* __restrict__ out, int N)
{
    extern __shared__ __align__(16) float smem[];
    float* hs   = smem + SM_HS;     // hidden, stride 33
    float* pp   = smem + SM_PP;     // partials / KAN ps
    float* cw0p = smem + SM_CW0;    // coef0*ws0, [i][j+4 (20)][o6], zero-padded
    float* wb0s = smem + SM_WB0;
    float* cw1p = smem + SM_CW1;    // coef1*ws1, [i][j+4 (20)], zero-padded
    float* wb1s = smem + SM_WB1;
    float* b0s  = smem + SM_B0;
    float* b1s  = smem + SM_B1;

    const int tid  = threadIdx.x;
    const int warp = tid >> 5;
    const int lane = tid & 31;
    const int g    = lane >> 2;
    const int t4   = lane & 3;
    const int wp   = warp & 3;        // m-pair id (rows wp*32..wp*32+31)
    const int kh   = warp >> 2;       // k-half (0: steps 0..30, 1: 31..61)
    const int off  = kh * KSPLIT;
    const int row0 = blockIdx.x * TMROWS;

    // ---- stage KAN tables (zero-padded j range: jj = j+4 in 0..19) ----
    for (int idx = tid; idx < 32 * 20 * 6; idx += 256) {
        int i = idx / 120, rem = idx % 120, jj = rem / 6, o = rem % 6;
        int j = jj - 4;
        cw0p[idx] = (j >= 0 && j < 12)
                  ? coef0[(i * 6 + o) * 12 + j] * ws0[i * 6 + o] : 0.f;
    }
    if (tid < 32 * 6) wb0s[tid] = wb0[tid];
    if (tid < 120) {
        int i = tid / 20, jj = tid % 20, j = jj - 4;
        cw1p[tid] = (j >= 0 && j < 12) ? coef1[i * 12 + j] * ws1[i] : 0.f;
    }
    if (tid < 6)  { wb1s[tid] = wb1[tid]; b0s[tid] = b0[tid]; }
    if (tid == 0) b1s[0] = b1[0];

    // ---- A row pointers for the 2 m-tiles ----
    const float* pA[2][2];
    #pragma unroll
    for (int mt = 0; mt < 2; mt++) {
        int r0 = row0 + (wp * 2 + mt) * 16 + g;
        int r1 = r0 + 8;
        if (r0 > N - 1) r0 = N - 1;
        if (r1 > N - 1) r1 = N - 1;
        pA[mt][0] = A + (size_t)r0 * D_IN + t4 * 4;
        pA[mt][1] = A + (size_t)r1 * D_IN + t4 * 4;
    }

    // ---- prefetch step `off` (A and W, depth 1) ----
    float4 av[2][2];
    uint4  wv[4];
    #pragma unroll
    for (int mt = 0; mt < 2; mt++) {
        av[mt][0] = __ldcs((const float4*)(pA[mt][0] + off * 16));
        av[mt][1] = __ldcs((const float4*)(pA[mt][1] + off * 16));
    }
    {
        const uint4* wq = &g_Wf[(size_t)(off * 4) * 32 + lane];
        #pragma unroll
        for (int nt = 0; nt < 4; nt++) wv[nt] = wq[nt * 32];
    }

    float acc[2][4][4];
    #pragma unroll
    for (int mt = 0; mt < 2; mt++)
        #pragma unroll
        for (int nt = 0; nt < 4; nt++)
            #pragma unroll
            for (int r = 0; r < 4; r++) acc[mt][nt][r] = 0.f;

    // ---- mainloop: 31 k-steps, 2 m-tiles per step, barrier-free ----
    for (int s = 0; s < KSPLIT; s++) {
        float4 a0[2], a1[2];
        uint4  w[4];
        #pragma unroll
        for (int mt = 0; mt < 2; mt++) { a0[mt] = av[mt][0]; a1[mt] = av[mt][1]; }
        #pragma unroll
        for (int nt = 0; nt < 4; nt++) w[nt] = wv[nt];

        if (s + 1 < KSPLIT) {
            const int kn = off + s + 1;
            #pragma unroll
            for (int mt = 0; mt < 2; mt++) {
                av[mt][0] = __ldcs((const float4*)(pA[mt][0] + kn * 16));
                av[mt][1] = __ldcs((const float4*)(pA[mt][1] + kn * 16));
            }
            const uint4* wq = &g_Wf[(size_t)(kn * 4) * 32 + lane];
            #pragma unroll
            for (int nt = 0; nt < 4; nt++) wv[nt] = wq[nt * 32];
        }

        #pragma unroll
        for (int mt = 0; mt < 2; mt++) {
            uint32_t ah0 = packbf(a0[mt].x, a0[mt].y);
            uint32_t ah1 = packbf(a1[mt].x, a1[mt].y);
            uint32_t ah2 = packbf(a0[mt].z, a0[mt].w);
            uint32_t ah3 = packbf(a1[mt].z, a1[mt].w);

            float e0, e1;
            uint32_t al0, al1, al2, al3;
            unpackbf(ah0, e0, e1); al0 = packbf(a0[mt].x - e0, a0[mt].y - e1);
            unpackbf(ah1, e0, e1); al1 = packbf(a1[mt].x - e0, a1[mt].y - e1);
            unpackbf(ah2, e0, e1); al2 = packbf(a0[mt].z - e0, a0[mt].w - e1);
            unpackbf(ah3, e0, e1); al3 = packbf(a1[mt].z - e0, a1[mt].w - e1);

            #pragma unroll
            for (int nt = 0; nt < 4; nt++) {
                mma_bf16(acc[mt][nt], ah0, ah1, ah2, ah3, w[nt].x, w[nt].y);
                mma_bf16(acc[mt][nt], ah0, ah1, ah2, ah3, w[nt].z, w[nt].w);
                mma_bf16(acc[mt][nt], al0, al1, al2, al3, w[nt].x, w[nt].y);
            }
        }
    }

    // ---- combine halves: upper dumps partials, lower adds + bias + transpose
    if (kh == 1) {
        #pragma unroll
        for (int nt = 0; nt < 4; nt++)
            #pragma unroll
            for (int mt = 0; mt < 2; mt++) {
                int rl = (wp * 2 + mt) * 16 + g;
                int c0 = nt * 8 + t4 * 2;
                pp[rl * 33 + c0]           = acc[mt][nt][0];
                pp[rl * 33 + c0 + 1]       = acc[mt][nt][1];
                pp[(rl + 8) * 33 + c0]     = acc[mt][nt][2];
                pp[(rl + 8) * 33 + c0 + 1] = acc[mt][nt][3];
            }
    }
    __syncthreads();
    if (kh == 0) {
        #pragma unroll
        for (int nt = 0; nt < 4; nt++) {
            float2 bv = *(const float2*)&bias[nt * 8 + t4 * 2];
            #pragma unroll
            for (int mt = 0; mt < 2; mt++) {
                int rl = (wp * 2 + mt) * 16 + g;
                int c0 = nt * 8 + t4 * 2;
                hs[rl * 33 + c0]           = acc[mt][nt][0] + pp[rl * 33 + c0]           + bv.x;
                hs[rl * 33 + c0 + 1]       = acc[mt][nt][1] + pp[rl * 33 + c0 + 1]       + bv.y;
                hs[(rl + 8) * 33 + c0]     = acc[mt][nt][2] + pp[(rl + 8) * 33 + c0]     + bv.x;
                hs[(rl + 8) * 33 + c0 + 1] = acc[mt][nt][3] + pp[(rl + 8) * 33 + c0 + 1] + bv.y;
            }
        }
    }
    __syncthreads();

    // ---- KAN layer 0: 2 threads per row, each handles 16 of 32 inputs ----
    const int r = tid & 127;          // row within CTA
    const int h = tid >> 7;           // half (0: i 0..15, 1: i 16..31)

    uint64_t kacc[3];
    kacc[0] = kacc[1] = kacc[2] = 0ull;

    #pragma unroll
    for (int i2 = 0; i2 < 16; i2++) {
        const int i = h * 16 + i2;
        float x  = hs[r * 33 + i];
        float sg = silu_f(x);
        uint64_t sgd = f2dup(sg);
        const uint64_t* wbp = (const uint64_t*)&wb0s[i * 6];
        ffma2(kacc[0], sgd, wbp[0]);
        ffma2(kacc[1], sgd, wbp[1]);
        ffma2(kacc[2], sgd, wbp[2]);

        float t = (x + 2.f) * 4.f;
        if (t >= 0.f && t < 16.f) {
            float cf = floorf(t);
            int   c  = (int)cf;
            float u  = t - cf;
            float bw[5];
            bspline4(u, bw);
            const float* base = &cw0p[i * 120 + c * 6];   // tap k -> base + k*6
            #pragma unroll
            for (int k = 0; k < 5; k++) {
                uint64_t bd = f2dup(bw[k]);
                const uint64_t* cp = (const uint64_t*)(base + k * 6);
                ffma2(kacc[0], bd, cp[0]);
                ffma2(kacc[1], bd, cp[1]);
                ffma2(kacc[2], bd, cp[2]);
            }
        }
    }
    __syncthreads();                     // pp free for reuse as partial buffer
    {
        float p0, p1, p2, p3, p4, p5;
        f2unpack(kacc[0], p0, p1);
        f2unpack(kacc[1], p2, p3);
        f2unpack(kacc[2], p4, p5);
        float* q = &pp[r * 12 + h * 6];
        q[0] = p0; q[1] = p1; q[2] = p2;
        q[3] = p3; q[4] = p4; q[5] = p5;
    }
    __syncthreads();

    // ---- KAN layer 1 (half 0 threads only) ----
    if (h == 0) {
        const int row = row0 + r;
        if (row < N) {
            float res = b1s[0];
            #pragma unroll
            for (int i = 0; i < 6; i++) {
                float x = pp[r * 12 + i] + pp[r * 12 + 6 + i] + b0s[i];
                res += silu_f(x) * wb1s[i];
                float t = (x + 2.f) * 4.f;
                if (t >= 0.f && t < 16.f) {
                    float cf = floorf(t);
                    int   c  = (int)cf;
                    float u  = t - cf;
                    float bw[5];
                    bspline4(u, bw);
                    const float* base = &cw1p[i * 20 + c];
                    #pragma unroll
                    for (int k = 0; k < 5; k++)
                        res += bw[k] * base[k];
                }
            }
            out[row] = res;
        }
    }
}

// ---------------------------------------------------------------------------
// Launch
// ---------------------------------------------------------------------------
extern "C" void kernel_launch(void* const* d_in, const int* in_sizes, int n_in,
                              void* d_out, int out_size)
{
    const float* node_rep = (const float*)d_in[0];
    const float* mlp_w    = (const float*)d_in[1];
    const float* mlp_b    = (const float*)d_in[2];
    const float* coef0    = (const float*)d_in[3];
    const float* wb0      = (const float*)d_in[4];
    const float* ws0      = (const float*)d_in[5];
    const float* b0       = (const float*)d_in[6];
    const float* coef1    = (const float*)d_in[7];
    const float* wb1      = (const float*)d_in[8];
    const float* ws1      = (const float*)d_in[9];
    const float* b1       = (const float*)d_in[10];

    int N = in_sizes[0] / D_IN;

    cudaFuncSetAttribute(fused_kernel,
                         cudaFuncAttributeMaxDynamicSharedMemorySize, SM_BYTES);

    wfrag_kernel<<<(NKS * 4 * 32 + 255) / 256, 256>>>(mlp_w);
    fused_kernel<<<(N + TMROWS - 1) / TMROWS, 256, SM_BYTES>>>(
        node_rep, mlp_b, coef0, wb0, ws0, b0, coef1, wb1, ws1, b1,
        (float*)d_out, N);
}

// round 10
// speedup vs baseline: 1.3062x; 1.0131x over previous
#include <cuda_runtime.h>
#include <cuda_bf16.h>
#include <cstdint>

// ---------------------------------------------------------------------------
// Problem constants
// ---------------------------------------------------------------------------
#define D_IN   992
#define HID    32
#define NKS    62            // 992 / 16 k-steps
#define KSPLIT 31            // k-steps per warp (2-way split)
#define TMROWS 128           // rows per CTA

// W in mma B-fragment layout (k-permuted), bf16 hi/lo packed per lane:
// [ks 62][nt 4][lane 32] -> uint4 (bh0, bh1, bl0, bl1)
__device__ uint4 g_Wf[NKS * 4 * 32];

// ---------------------------------------------------------------------------
// dynamic smem layout (floats)
// ---------------------------------------------------------------------------
#define SM_HS   0                          // 128*33 = 4224
#define SM_PP   4224                       // 128*33 = 4224
#define SM_CW0  8448                       // 32*20*6 = 3840 (j padded -4..15)
#define SM_WB0  12288                      // 32*6 = 192
#define SM_CW1  12480                      // 6*20 = 120 (j padded)
#define SM_WB1  12600                      // 6
#define SM_B0   12606                      // 6
#define SM_B1   12612                      // 1
#define SM_TOTF 12616
#define SM_BYTES (SM_TOTF * 4)             // 50464

// ---------------------------------------------------------------------------
// helpers
// ---------------------------------------------------------------------------
__device__ __forceinline__ uint32_t packbf(float e0, float e1) {
    uint32_t r;
    asm("cvt.rn.bf16x2.f32 %0, %1, %2;" : "=r"(r) : "f"(e1), "f"(e0));
    return r;
}
__device__ __forceinline__ void unpackbf(uint32_t p, float& e0, float& e1) {
    e0 = __uint_as_float(p << 16);
    e1 = __uint_as_float(p & 0xFFFF0000u);
}
__device__ __forceinline__ void mma_bf16(float d[4], uint32_t a0, uint32_t a1,
                                         uint32_t a2, uint32_t a3,
                                         uint32_t b0, uint32_t b1) {
    asm volatile(
        "mma.sync.aligned.m16n8k16.row.col.f32.bf16.bf16.f32 "
        "{%0,%1,%2,%3}, {%4,%5,%6,%7}, {%8,%9}, {%0,%1,%2,%3};"
        : "+f"(d[0]), "+f"(d[1]), "+f"(d[2]), "+f"(d[3])
        : "r"(a0), "r"(a1), "r"(a2), "r"(a3), "r"(b0), "r"(b1));
}

// f32x2 packed helpers (KAN phase)
__device__ __forceinline__ uint64_t f2dup(float x) {
    uint64_t r; asm("mov.b64 %0, {%1, %1};" : "=l"(r) : "f"(x)); return r;
}
__device__ __forceinline__ void f2unpack(uint64_t v, float& x, float& y) {
    asm("mov.b64 {%0, %1}, %2;" : "=f"(x), "=f"(y) : "l"(v));
}
__device__ __forceinline__ void ffma2(uint64_t& d, uint64_t a, uint64_t b) {
    asm("fma.rn.f32x2 %0, %1, %2, %0;" : "+l"(d) : "l"(a), "l"(b));
}

// degree-4 uniform B-spline basis (5 nonzero values), matches reference
__device__ __forceinline__ void bspline4(float u, float bw[5]) {
    const float um = 1.f - u;
    float c0 = um, c1 = u;
    float d0 = 0.5f * (um * c0);
    float d1 = 0.5f * ((u + 1.f) * c0 + (2.f - u) * c1);
    float d2 = 0.5f * (u * c1);
    const float i3 = 1.f / 3.f;
    float e0 = i3 * (um * d0);
    float e1 = i3 * ((u + 2.f) * d0 + (2.f - u) * d1);
    float e2 = i3 * ((u + 1.f) * d1 + (3.f - u) * d2);
    float e3 = i3 * (u * d2);
    bw[0] = 0.25f * (um * e0);
    bw[1] = 0.25f * ((u + 3.f) * e0 + (2.f - u) * e1);
    bw[2] = 0.25f * ((u + 2.f) * e1 + (3.f - u) * e2);
    bw[3] = 0.25f * ((u + 1.f) * e2 + (4.f - u) * e3);
    bw[4] = 0.25f * (u * e3);
}
__device__ __forceinline__ float silu_f(float x) { return x / (1.f + __expf(-x)); }

// ---------------------------------------------------------------------------
// W pre-conversion with k-permutation:
// lane (g,t4), nt: b0 = {W[ks16+4t4][n], W[ks16+4t4+1][n]},
//                  b1 = {W[ks16+4t4+2][n], W[ks16+4t4+3][n]}, n = nt*8+g
// ---------------------------------------------------------------------------
__global__ void wfrag_kernel(const float* __restrict__ W) {
    int idx = blockIdx.x * 256 + threadIdx.x;     // 62*4*32 = 7936
    if (idx >= NKS * 4 * 32) return;
    int lane = idx & 31;
    int nt   = (idx >> 5) & 3;
    int ks   = idx >> 7;
    int g = lane >> 2, t4 = lane & 3;
    int n  = nt * 8 + g;
    int ka = ks * 16 + t4 * 4;

    float x0 = W[(ka + 0) * HID + n];
    float x1 = W[(ka + 1) * HID + n];
    float y0 = W[(ka + 2) * HID + n];
    float y1 = W[(ka + 3) * HID + n];

    uint32_t h0 = packbf(x0, x1), h1 = packbf(y0, y1);
    float e0, e1;
    unpackbf(h0, e0, e1);
    uint32_t l0 = packbf(x0 - e0, x1 - e1);
    unpackbf(h1, e0, e1);
    uint32_t l1 = packbf(y0 - e0, y1 - e1);

    g_Wf[idx] = make_uint4(h0, h1, l0, l1);
}

// ---------------------------------------------------------------------------
// One GEMM k-step on buffer BUF (compile-time literal!):
//   consume av[BUF], immediately refill av[BUF] with step KPRE (clamped,
//   branch-free), load W for step KS in-step (L1-resident), 12 mma.
// ---------------------------------------------------------------------------
#define GEMM_STEP(BUF, KS, KPRE)                                               \
{                                                                              \
    float4 a0[2], a1[2];                                                       \
    _Pragma("unroll")                                                          \
    for (int mt = 0; mt < 2; mt++) {                                           \
        a0[mt] = av[BUF][mt][0];                                               \
        a1[mt] = av[BUF][mt][1];                                               \
    }                                                                          \
    {                                                                          \
        const int _kp = (KPRE);                                                \
        _Pragma("unroll")                                                      \
        for (int mt = 0; mt < 2; mt++) {                                       \
            av[BUF][mt][0] = __ldcs((const float4*)(pA[mt][0] + _kp * 16));    \
            av[BUF][mt][1] = __ldcs((const float4*)(pA[mt][1] + _kp * 16));    \
        }                                                                      \
    }                                                                          \
    uint4 w[4];                                                                \
    {                                                                          \
        const uint4* wq = &g_Wf[(size_t)((KS) * 4) * 32 + lane];               \
        _Pragma("unroll")                                                      \
        for (int nt = 0; nt < 4; nt++) w[nt] = wq[nt * 32];                    \
    }                                                                          \
    _Pragma("unroll")                                                          \
    for (int mt = 0; mt < 2; mt++) {                                           \
        uint32_t ah0 = packbf(a0[mt].x, a0[mt].y);                             \
        uint32_t ah1 = packbf(a1[mt].x, a1[mt].y);                             \
        uint32_t ah2 = packbf(a0[mt].z, a0[mt].w);                             \
        uint32_t ah3 = packbf(a1[mt].z, a1[mt].w);                             \
        float e0, e1;                                                          \
        uint32_t al0, al1, al2, al3;                                           \
        unpackbf(ah0, e0, e1); al0 = packbf(a0[mt].x - e0, a0[mt].y - e1);     \
        unpackbf(ah1, e0, e1); al1 = packbf(a1[mt].x - e0, a1[mt].y - e1);     \
        unpackbf(ah2, e0, e1); al2 = packbf(a0[mt].z - e0, a0[mt].w - e1);     \
        unpackbf(ah3, e0, e1); al3 = packbf(a1[mt].z - e0, a1[mt].w - e1);     \
        _Pragma("unroll")                                                      \
        for (int nt = 0; nt < 4; nt++) {                                       \
            mma_bf16(acc[mt][nt], ah0, ah1, ah2, ah3, w[nt].x, w[nt].y);       \
            mma_bf16(acc[mt][nt], ah0, ah1, ah2, ah3, w[nt].z, w[nt].w);       \
            mma_bf16(acc[mt][nt], al0, al1, al2, al3, w[nt].x, w[nt].y);       \
        }                                                                      \
    }                                                                          \
}

// ---------------------------------------------------------------------------
// Fused kernel (R9 + depth-2 A register prefetch, literal buffer indices):
//   warp w (w<4)  : m-tiles 2w, 2w+1 (rows w*32..w*32+31), k-steps 0..30
//   warp w+4      : same m-tiles,                          k-steps 31..61
// ---------------------------------------------------------------------------
__global__ void __launch_bounds__(256, 2)
fused_kernel(const float* __restrict__ A, const float* __restrict__ bias,
             const float* __restrict__ coef0, const float* __restrict__ wb0,
             const float* __restrict__ ws0,   const float* __restrict__ b0,
             const float* __restrict__ coef1, const float* __restrict__ wb1,
             const float* __restrict__ ws1,   const float* __restrict__ b1,
             float* __restrict__ out, int N)
{
    extern __shared__ __align__(16) float smem[];
    float* hs   = smem + SM_HS;     // hidden, stride 33
    float* pp   = smem + SM_PP;     // partials / KAN ps
    float* cw0p = smem + SM_CW0;    // coef0*ws0, [i][j+4 (20)][o6], zero-padded
    float* wb0s = smem + SM_WB0;
    float* cw1p = smem + SM_CW1;    // coef1*ws1, [i][j+4 (20)], zero-padded
    float* wb1s = smem + SM_WB1;
    float* b0s  = smem + SM_B0;
    float* b1s  = smem + SM_B1;

    const int tid  = threadIdx.x;
    const int warp = tid >> 5;
    const int lane = tid & 31;
    const int g    = lane >> 2;
    const int t4   = lane & 3;
    const int wp   = warp & 3;        // m-pair id (rows wp*32..wp*32+31)
    const int kh   = warp >> 2;       // k-half (0: steps 0..30, 1: 31..61)
    const int off  = kh * KSPLIT;
    const int row0 = blockIdx.x * TMROWS;

    // ---- stage KAN tables (zero-padded j range: jj = j+4 in 0..19) ----
    for (int idx = tid; idx < 32 * 20 * 6; idx += 256) {
        int i = idx / 120, rem = idx % 120, jj = rem / 6, o = rem % 6;
        int j = jj - 4;
        cw0p[idx] = (j >= 0 && j < 12)
                  ? coef0[(i * 6 + o) * 12 + j] * ws0[i * 6 + o] : 0.f;
    }
    if (tid < 32 * 6) wb0s[tid] = wb0[tid];
    if (tid < 120) {
        int i = tid / 20, jj = tid % 20, j = jj - 4;
        cw1p[tid] = (j >= 0 && j < 12) ? coef1[i * 12 + j] * ws1[i] : 0.f;
    }
    if (tid < 6)  { wb1s[tid] = wb1[tid]; b0s[tid] = b0[tid]; }
    if (tid == 0) b1s[0] = b1[0];

    // ---- A row pointers for the 2 m-tiles ----
    const float* pA[2][2];
    #pragma unroll
    for (int mt = 0; mt < 2; mt++) {
        int r0 = row0 + (wp * 2 + mt) * 16 + g;
        int r1 = r0 + 8;
        if (r0 > N - 1) r0 = N - 1;
        if (r1 > N - 1) r1 = N - 1;
        pA[mt][0] = A + (size_t)r0 * D_IN + t4 * 4;
        pA[mt][1] = A + (size_t)r1 * D_IN + t4 * 4;
    }

    // ---- depth-2 A prefetch: av[buf][mt][half], buf index always literal ----
    float4 av[2][2][2];
    #pragma unroll
    for (int mt = 0; mt < 2; mt++) {
        av[0][mt][0] = __ldcs((const float4*)(pA[mt][0] + off * 16));
        av[0][mt][1] = __ldcs((const float4*)(pA[mt][1] + off * 16));
        av[1][mt][0] = __ldcs((const float4*)(pA[mt][0] + (off + 1) * 16));
        av[1][mt][1] = __ldcs((const float4*)(pA[mt][1] + (off + 1) * 16));
    }

    float acc[2][4][4];
    #pragma unroll
    for (int mt = 0; mt < 2; mt++)
        #pragma unroll
        for (int nt = 0; nt < 4; nt++)
            #pragma unroll
            for (int r = 0; r < 4; r++) acc[mt][nt][r] = 0.f;

    // ---- mainloop: 31 k-steps, pairs of 2, barrier-free ----
    // pair loop covers steps 0..29; final step 30 handled after.
    for (int s = 0; s + 1 < KSPLIT; s += 2) {
        const int p0 = (s + 2 < KSPLIT) ? s + 2 : KSPLIT - 1;
        const int p1 = (s + 3 < KSPLIT) ? s + 3 : KSPLIT - 1;
        GEMM_STEP(0, off + s,     off + p0);
        GEMM_STEP(1, off + s + 1, off + p1);
    }
    GEMM_STEP(0, off + KSPLIT - 1, off + KSPLIT - 1);   // step 30 (refill redundant)

    // ---- combine halves: upper dumps partials, lower adds + bias + transpose
    if (kh == 1) {
        #pragma unroll
        for (int nt = 0; nt < 4; nt++)
            #pragma unroll
            for (int mt = 0; mt < 2; mt++) {
                int rl = (wp * 2 + mt) * 16 + g;
                int c0 = nt * 8 + t4 * 2;
                pp[rl * 33 + c0]           = acc[mt][nt][0];
                pp[rl * 33 + c0 + 1]       = acc[mt][nt][1];
                pp[(rl + 8) * 33 + c0]     = acc[mt][nt][2];
                pp[(rl + 8) * 33 + c0 + 1] = acc[mt][nt][3];
            }
    }
    __syncthreads();
    if (kh == 0) {
        #pragma unroll
        for (int nt = 0; nt < 4; nt++) {
            float2 bv = *(const float2*)&bias[nt * 8 + t4 * 2];
            #pragma unroll
            for (int mt = 0; mt < 2; mt++) {
                int rl = (wp * 2 + mt) * 16 + g;
                int c0 = nt * 8 + t4 * 2;
                hs[rl * 33 + c0]           = acc[mt][nt][0] + pp[rl * 33 + c0]           + bv.x;
                hs[rl * 33 + c0 + 1]       = acc[mt][nt][1] + pp[rl * 33 + c0 + 1]       + bv.y;
                hs[(rl + 8) * 33 + c0]     = acc[mt][nt][2] + pp[(rl + 8) * 33 + c0]     + bv.x;
                hs[(rl + 8) * 33 + c0 + 1] = acc[mt][nt][3] + pp[(rl + 8) * 33 + c0 + 1] + bv.y;
            }
        }
    }
    __syncthreads();

    // ---- KAN layer 0: 2 threads per row, each handles 16 of 32 inputs ----
    const int r = tid & 127;          // row within CTA
    const int h = tid >> 7;           // half (0: i 0..15, 1: i 16..31)

    uint64_t kacc[3];
    kacc[0] = kacc[1] = kacc[2] = 0ull;

    #pragma unroll
    for (int i2 = 0; i2 < 16; i2++) {
        const int i = h * 16 + i2;
        float x  = hs[r * 33 + i];
        float sg = silu_f(x);
        uint64_t sgd = f2dup(sg);
        const uint64_t* wbp = (const uint64_t*)&wb0s[i * 6];
        ffma2(kacc[0], sgd, wbp[0]);
        ffma2(kacc[1], sgd, wbp[1]);
        ffma2(kacc[2], sgd, wbp[2]);

        float t = (x + 2.f) * 4.f;
        if (t >= 0.f && t < 16.f) {
            float cf = floorf(t);
            int   c  = (int)cf;
            float u  = t - cf;
            float bw[5];
            bspline4(u, bw);
            const float* base = &cw0p[i * 120 + c * 6];   // tap k -> base + k*6
            #pragma unroll
            for (int k = 0; k < 5; k++) {
                uint64_t bd = f2dup(bw[k]);
                const uint64_t* cp = (const uint64_t*)(base + k * 6);
                ffma2(kacc[0], bd, cp[0]);
                ffma2(kacc[1], bd, cp[1]);
                ffma2(kacc[2], bd, cp[2]);
            }
        }
    }
    __syncthreads();                     // pp free for reuse as partial buffer
    {
        float p0, p1, p2, p3, p4, p5;
        f2unpack(kacc[0], p0, p1);
        f2unpack(kacc[1], p2, p3);
        f2unpack(kacc[2], p4, p5);
        float* q = &pp[r * 12 + h * 6];
        q[0] = p0; q[1] = p1; q[2] = p2;
        q[3] = p3; q[4] = p4; q[5] = p5;
    }
    __syncthreads();

    // ---- KAN layer 1 (half 0 threads only) ----
    if (h == 0) {
        const int row = row0 + r;
        if (row < N) {
            float res = b1s[0];
            #pragma unroll
            for (int i = 0; i < 6; i++) {
                float x = pp[r * 12 + i] + pp[r * 12 + 6 + i] + b0s[i];
                res += silu_f(x) * wb1s[i];
                float t = (x + 2.f) * 4.f;
                if (t >= 0.f && t < 16.f) {
                    float cf = floorf(t);
                    int   c  = (int)cf;
                    float u  = t - cf;
                    float bw[5];
                    bspline4(u, bw);
                    const float* base = &cw1p[i * 20 + c];
                    #pragma unroll
                    for (int k = 0; k < 5; k++)
                        res += bw[k] * base[k];
                }
            }
            out[row] = res;
        }
    }
}

// ---------------------------------------------------------------------------
// Launch
// ---------------------------------------------------------------------------
extern "C" void kernel_launch(void* const* d_in, const int* in_sizes, int n_in,
                              void* d_out, int out_size)
{
    const float* node_rep = (const float*)d_in[0];
    const float* mlp_w    = (const float*)d_in[1];
    const float* mlp_b    = (const float*)d_in[2];
    const float* coef0    = (const float*)d_in[3];
    const float* wb0      = (const float*)d_in[4];
    const float* ws0      = (const float*)d_in[5];
    const float* b0       = (const float*)d_in[6];
    const float* coef1    = (const float*)d_in[7];
    const float* wb1      = (const float*)d_in[8];
    const float* ws1      = (const float*)d_in[9];
    const float* b1       = (const float*)d_in[10];

    int N = in_sizes[0] / D_IN;

    cudaFuncSetAttribute(fused_kernel,
                         cudaFuncAttributeMaxDynamicSharedMemorySize, SM_BYTES);

    wfrag_kernel<<<(NKS * 4 * 32 + 255) / 256, 256>>>(mlp_w);
    fused_kernel<<<(N + TMROWS - 1) / TMROWS, 256, SM_BYTES>>>(
        node_rep, mlp_b, coef0, wb0, ws0, b0, coef1, wb1, ws1, b1,
        (float*)d_out, N);
}